// round 14
// baseline (speedup 1.0000x reference)
#include <cuda_runtime.h>
#include <stddef.h>
#include <stdint.h>

// Problem constants
#define C_CH   32
#define NROW   1024
#define D_DIM  768
#define BHALF  512
#define RSTRIDE (32 * 768)   // float stride between consecutive batch rows of a channel

// ---- scratch (device globals; no allocation allowed) ----
__device__ float  g_sq[C_CH * NROW];
__device__ float  g_colpart[C_CH * 8 * D_DIM];
__device__ float  g_negc[C_CH];
__device__ double g_acc[C_CH * 3];    // per channel: Sxx, Syy, (Sxy+Syx)
// pre-split fp16 operands, layout [c][row][d] contiguous per channel
__device__ uint16_t g_h[C_CH * NROW * D_DIM];   // 48 MB
__device__ uint16_t g_l[C_CH * NROW * D_DIM];   // 48 MB

__device__ __forceinline__ const float* row_base(const float* __restrict__ src,
                                                 const float* __restrict__ tgt,
                                                 int c, int i) {
    return (i < BHALF)
        ? src + ((size_t)i * 32 + c) * 768
        : tgt + ((size_t)(i - BHALF) * 32 + c) * 768;
}

// exp2 on the FMA pipe: valid for |x| < 2^22, here x in (-1, +eps]
__device__ __forceinline__ float fast_exp2(float x) {
    float r = x + 12582912.0f;
    int   n = __float_as_int(r);
    float f = x - (r - 12582912.0f);
    float p = 1.5403530e-4f;
    p = fmaf(p, f, 1.3333558e-3f);
    p = fmaf(p, f, 9.6181291e-3f);
    p = fmaf(p, f, 5.5504109e-2f);
    p = fmaf(p, f, 2.4022651e-1f);
    p = fmaf(p, f, 6.9314718e-1f);
    p = fmaf(p, f, 1.0f);
    return __int_as_float(__float_as_int(p) + (n << 23));
}

__device__ __forceinline__ uint32_t smem_u32(const void* p) {
    uint32_t a;
    asm("{ .reg .u64 t; cvta.to.shared.u64 t, %1; cvt.u32.u64 %0, t; }" : "=r"(a) : "l"(p));
    return a;
}
__device__ __forceinline__ void cp16(uint32_t dst, const void* src) {
    asm volatile("cp.async.cg.shared.global [%0], [%1], 16;" :: "r"(dst), "l"(src));
}
#define CP_COMMIT() asm volatile("cp.async.commit_group;" ::: "memory")
#define CP_WAIT(n)  asm volatile("cp.async.wait_group %0;" :: "n"(n) : "memory")

// split 2 floats -> fp16 hi half2 + fp16 lo half2 (hi = 10-bit trunc, exactly fp16; lo exact residual)
__device__ __forceinline__ void split2(float x, float y, uint32_t& h2, uint32_t& l2) {
    float h0 = __uint_as_float(__float_as_uint(x) & 0xFFFFE000u);
    float h1 = __uint_as_float(__float_as_uint(y) & 0xFFFFE000u);
    float l0 = x - h0;
    float l1 = y - h1;
    asm("cvt.rn.f16x2.f32 %0, %1, %2;" : "=r"(h2) : "f"(h1), "f"(h0));  // low half = x
    asm("cvt.rn.f16x2.f32 %0, %1, %2;" : "=r"(l2) : "f"(l1), "f"(l0));
}

// ---- P1: per-row squared norms + fused fp16 hi/lo split-write ----
__global__ void psq_kernel(const float* __restrict__ src, const float* __restrict__ tgt) {
    int c    = blockIdx.x;
    int warp = threadIdx.x >> 5, lane = threadIdx.x & 31;
    int i    = blockIdx.y * 8 + warp;
    const float4* rp = (const float4*)row_base(src, tgt, c, i);
    const size_t rowoff = ((size_t)c * NROW + i) * D_DIM;
    float s = 0.f;
#pragma unroll
    for (int j = 0; j < 6; ++j) {
        int f = lane + 32 * j;
        float4 v = rp[f];
        s += v.x * v.x + v.y * v.y + v.z * v.z + v.w * v.w;
        uint32_t h01, l01, h23, l23;
        split2(v.x, v.y, h01, l01);
        split2(v.z, v.w, h23, l23);
        *(uint2*)&g_h[rowoff + f * 4] = make_uint2(h01, h23);
        *(uint2*)&g_l[rowoff + f * 4] = make_uint2(l01, l23);
    }
#pragma unroll
    for (int off = 16; off; off >>= 1) s += __shfl_down_sync(0xffffffffu, s, off);
    if (lane == 0) g_sq[c * NROW + i] = s;
}

// ---- P2: partial column sums (for bandwidth) ----
__global__ void pcol_kernel(const float* __restrict__ src, const float* __restrict__ tgt) {
    int c = blockIdx.x, part = blockIdx.y;
    int t = threadIdx.x;
    float4 s = make_float4(0.f, 0.f, 0.f, 0.f);
    for (int r = 0; r < 128; ++r) {
        const float4* rp = (const float4*)row_base(src, tgt, c, part * 128 + r);
        float4 v = rp[t];
        s.x += v.x; s.y += v.y; s.z += v.z; s.w += v.w;
    }
    ((float4*)g_colpart)[(c * 8 + part) * 192 + t] = s;
}

// ---- P3: bandwidth coefficient per channel + zero accumulators ----
__global__ void pband_kernel() {
    int c = blockIdx.x, tid = threadIdx.x;
    __shared__ double sh[256];
    double acc = 0.0;
    for (int i = tid; i < NROW; i += 256)
        acc += 2.0 * (double)NROW * (double)g_sq[c * NROW + i];
    for (int d = tid; d < D_DIM; d += 256) {
        float cs = 0.f;
#pragma unroll
        for (int p = 0; p < 8; ++p) cs += g_colpart[(c * 8 + p) * D_DIM + d];
        acc -= 2.0 * (double)cs * (double)cs;
    }
    sh[tid] = acc;
    __syncthreads();
    for (int s = 128; s > 0; s >>= 1) {
        if (tid < s) sh[tid] += sh[tid + s];
        __syncthreads();
    }
    if (tid == 0) {
        double sumd2 = sh[0];
        double bw0 = sumd2 / ((double)NROW * NROW - NROW) / 4.0;
        double bw4 = bw0 * 16.0;
        g_negc[c] = (float)(-1.4426950408889634 / bw4);
        g_acc[c * 3 + 0] = 0.0;
        g_acc[c * 3 + 1] = 0.0;
        g_acc[c * 3 + 2] = 0.0;
    }
}

// ============ main kernel: fp16x3 mma.sync m16n8k16 GEMM + RBF epilogue ============
// Tile 128x128, BK=32 (halves), 2-stage double buffer. cp.async loads PRE-SPLIT fp16
// hi/lo tiles from g_h/g_l; MMA loop is pure LDS.32 fragment loads + tensor ops.
// dot = hi*hi + hi*lo + lo*hi (bit-identical numerics to the in-register split).
#define BM   128
#define BK   32    // halves per slab
#define LDKW 20    // fp16 tile row stride in half2 WORDS (40 halves, 80B/row; 64B data + pad)

// smem words per tile / stage
#define TILE_W   (BM * LDKW)                   // 2560
#define STAGE_W  (4 * TILE_W)                  // AH, AL, BH, BL = 10240
#define OFF_SQA  (2 * STAGE_W)                 // 20480
#define OFF_SQB  (OFF_SQA + BM)
#define OFF_RED  (OFF_SQB + BM)
#define SMEM_WORDS (OFF_RED + 256)             // 20992
#define SMEM_BYTES (SMEM_WORDS * 4)            // 83968

__device__ __forceinline__ void mma_f16(float& c0, float& c1, float& c2, float& c3,
                                        uint32_t a0, uint32_t a1, uint32_t a2, uint32_t a3,
                                        uint32_t b0, uint32_t b1) {
    asm volatile("mma.sync.aligned.m16n8k16.row.col.f32.f16.f16.f32 "
                 "{%0,%1,%2,%3}, {%4,%5,%6,%7}, {%8,%9}, {%0,%1,%2,%3};"
                 : "+f"(c0), "+f"(c1), "+f"(c2), "+f"(c3)
                 : "r"(a0), "r"(a1), "r"(a2), "r"(a3), "r"(b0), "r"(b1));
}

__global__ __launch_bounds__(256, 2) void mmd_gemm_kernel() {
    extern __shared__ uint32_t smw[];
    float* sqa_sm = (float*)(smw + OFF_SQA);
    float* sqb_sm = (float*)(smw + OFF_SQB);
    float* red    = (float*)(smw + OFF_RED);

    const int c = blockIdx.y;

    // tile index -> upper-triangular (bi, bj), bi <= bj
    int bi = 0, rem = blockIdx.x;
    while (rem >= (8 - bi)) { rem -= (8 - bi); ++bi; }
    const int bj = bi + rem;
    const int i0 = bi * BM, j0 = bj * BM;

    const int tid  = threadIdx.x;
    const int wid  = tid >> 5, lane = tid & 31;
    const int g    = lane >> 2;       // groupID (0..7)
    const int tig  = lane & 3;        // thread-in-group (0..3)
    const int wm0  = (wid >> 2) * 64;
    const int wn0  = (wid & 3) * 32;

    if (tid < 128) sqa_sm[tid] = g_sq[c * NROW + i0 + tid];
    else           sqb_sm[tid - 128] = g_sq[c * NROW + j0 + (tid - 128)];

    // loader mapping: 2 threads per tile row; each does 2 cp16 (32B) per tile
    const int lrow  = tid >> 1;        // 0..127
    const int lhalf = tid & 1;         // 0..1 -> halves [lhalf*16, lhalf*16+16)
    const uint16_t* gAh = g_h + ((size_t)c * NROW + i0 + lrow) * D_DIM + lhalf * 16;
    const uint16_t* gAl = g_l + ((size_t)c * NROW + i0 + lrow) * D_DIM + lhalf * 16;
    const uint16_t* gBh = g_h + ((size_t)c * NROW + j0 + lrow) * D_DIM + lhalf * 16;
    const uint16_t* gBl = g_l + ((size_t)c * NROW + j0 + lrow) * D_DIM + lhalf * 16;
    // smem dst byte offsets (stage 0): tile base + row*80 + lhalf*32
    const uint32_t sbase = smem_u32(smw);
    const uint32_t dstRow = (uint32_t)(lrow * (LDKW * 4) + lhalf * 32);
    const uint32_t dAH = sbase + 0 * (TILE_W * 4) + dstRow;
    const uint32_t dAL = sbase + 1 * (TILE_W * 4) + dstRow;
    const uint32_t dBH = sbase + 2 * (TILE_W * 4) + dstRow;
    const uint32_t dBL = sbase + 3 * (TILE_W * 4) + dstRow;
    const uint32_t stageBy = (uint32_t)(STAGE_W * 4);

    float cacc[4][4][4];
#pragma unroll
    for (int ma = 0; ma < 4; ++ma)
#pragma unroll
        for (int na = 0; na < 4; ++na)
#pragma unroll
            for (int q = 0; q < 4; ++q) cacc[ma][na][q] = 0.f;

    const int NK = D_DIM / BK;   // 24

    // preload slab 0 into stage 0
    cp16(dAH, gAh);      cp16(dAH + 16, gAh + 8);
    cp16(dAL, gAl);      cp16(dAL + 16, gAl + 8);
    cp16(dBH, gBh);      cp16(dBH + 16, gBh + 8);
    cp16(dBL, gBl);      cp16(dBL + 16, gBl + 8);
    CP_COMMIT();

    for (int ks = 0; ks < NK; ++ks) {
        const int s = ks & 1;
        if (ks + 1 < NK) {
            const int k0 = (ks + 1) * BK;      // half offset
            const uint32_t so = ((ks + 1) & 1) ? stageBy : 0u;
            cp16(dAH + so, gAh + k0);  cp16(dAH + so + 16, gAh + k0 + 8);
            cp16(dAL + so, gAl + k0);  cp16(dAL + so + 16, gAl + k0 + 8);
            cp16(dBH + so, gBh + k0);  cp16(dBH + so + 16, gBh + k0 + 8);
            cp16(dBL + so, gBl + k0);  cp16(dBL + so + 16, gBl + k0 + 8);
            CP_COMMIT();
            CP_WAIT(1);
        } else {
            CP_WAIT(0);
        }
        __syncthreads();

        const uint32_t* AH = smw + s * STAGE_W + 0 * TILE_W;
        const uint32_t* AL = smw + s * STAGE_W + 1 * TILE_W;
        const uint32_t* BH = smw + s * STAGE_W + 2 * TILE_W;
        const uint32_t* BL = smw + s * STAGE_W + 3 * TILE_W;

#pragma unroll
        for (int kk2 = 0; kk2 < BK / 2; kk2 += 8) {   // k offset in half2 words
            uint32_t ah[4][4], al[4][4], bh[4][2], bl[4][2];
#pragma unroll
            for (int ma = 0; ma < 4; ++ma) {
                const int base = (wm0 + ma * 16 + g) * LDKW + kk2 + tig;
                ah[ma][0] = AH[base];
                ah[ma][1] = AH[base + 8 * LDKW];
                ah[ma][2] = AH[base + 4];
                ah[ma][3] = AH[base + 8 * LDKW + 4];
                al[ma][0] = AL[base];
                al[ma][1] = AL[base + 8 * LDKW];
                al[ma][2] = AL[base + 4];
                al[ma][3] = AL[base + 8 * LDKW + 4];
            }
#pragma unroll
            for (int na = 0; na < 4; ++na) {
                const int base = (wn0 + na * 8 + g) * LDKW + kk2 + tig;
                bh[na][0] = BH[base];
                bh[na][1] = BH[base + 4];
                bl[na][0] = BL[base];
                bl[na][1] = BL[base + 4];
            }
            // pass 1: hi x hi
#pragma unroll
            for (int ma = 0; ma < 4; ++ma)
#pragma unroll
                for (int na = 0; na < 4; ++na)
                    mma_f16(cacc[ma][na][0], cacc[ma][na][1], cacc[ma][na][2], cacc[ma][na][3],
                            ah[ma][0], ah[ma][1], ah[ma][2], ah[ma][3],
                            bh[na][0], bh[na][1]);
            // pass 2: hi x lo
#pragma unroll
            for (int ma = 0; ma < 4; ++ma)
#pragma unroll
                for (int na = 0; na < 4; ++na)
                    mma_f16(cacc[ma][na][0], cacc[ma][na][1], cacc[ma][na][2], cacc[ma][na][3],
                            ah[ma][0], ah[ma][1], ah[ma][2], ah[ma][3],
                            bl[na][0], bl[na][1]);
            // pass 3: lo x hi
#pragma unroll
            for (int ma = 0; ma < 4; ++ma)
#pragma unroll
                for (int na = 0; na < 4; ++na)
                    mma_f16(cacc[ma][na][0], cacc[ma][na][1], cacc[ma][na][2], cacc[ma][na][3],
                            al[ma][0], al[ma][1], al[ma][2], al[ma][3],
                            bh[na][0], bh[na][1]);
        }
        __syncthreads();
    }

    // ---- epilogue: d2 -> 5-bandwidth RBF sum via one exp2 + 4 squarings ----
    const float negc = g_negc[c];
    float local = 0.f;
#pragma unroll
    for (int ma = 0; ma < 4; ++ma) {
        const float sq_r0 = sqa_sm[wm0 + ma * 16 + g];
        const float sq_r1 = sqa_sm[wm0 + ma * 16 + g + 8];
#pragma unroll
        for (int na = 0; na < 4; ++na) {
            const float sq_c0 = sqb_sm[wn0 + na * 8 + tig * 2];
            const float sq_c1 = sqb_sm[wn0 + na * 8 + tig * 2 + 1];
            float d2v[4];
            d2v[0] = fmaf(-2.0f, cacc[ma][na][0], sq_r0 + sq_c0);
            d2v[1] = fmaf(-2.0f, cacc[ma][na][1], sq_r0 + sq_c1);
            d2v[2] = fmaf(-2.0f, cacc[ma][na][2], sq_r1 + sq_c0);
            d2v[3] = fmaf(-2.0f, cacc[ma][na][3], sq_r1 + sq_c1);
#pragma unroll
            for (int q = 0; q < 4; ++q) {
                float e4 = fast_exp2(d2v[q] * negc);
                float e3 = e4 * e4;
                float e2 = e3 * e3;
                float e1 = e2 * e2;
                float e0 = e1 * e1;
                local += ((e0 + e1) + (e2 + e3)) + e4;
            }
        }
    }

    red[tid] = local;
    __syncthreads();
    for (int s = 128; s > 0; s >>= 1) {
        if (tid < s) red[tid] += red[tid + s];
        __syncthreads();
    }
    if (tid == 0) {
        int region = (bj < 4) ? 0 : ((bi >= 4) ? 1 : 2);   // XX / YY / XY
        double w = (bi == bj) ? 1.0 : 2.0;                 // symmetry weight
        atomicAdd(&g_acc[c * 3 + region], w * (double)red[0]);
    }
}

// ---- finalize: mean over channels of (Sxx + Syy - (Sxy+Syx)) / B^2 ----
__global__ void final_kernel(float* __restrict__ out) {
    int c = threadIdx.x;   // 32 threads
    double mmd = (g_acc[c * 3 + 0] + g_acc[c * 3 + 1] - g_acc[c * 3 + 2])
                 * (1.0 / (512.0 * 512.0));
#pragma unroll
    for (int off = 16; off; off >>= 1)
        mmd += __shfl_down_sync(0xffffffffu, mmd, off);
    if (c == 0) out[0] = (float)(mmd / 32.0);
}

extern "C" void kernel_launch(void* const* d_in, const int* in_sizes, int n_in,
                              void* d_out, int out_size) {
    const float* src = (const float*)d_in[0];
    const float* tgt = (const float*)d_in[1];
    float* out = (float*)d_out;

    cudaFuncSetAttribute(mmd_gemm_kernel, cudaFuncAttributeMaxDynamicSharedMemorySize, SMEM_BYTES);

    psq_kernel<<<dim3(32, 128), 256>>>(src, tgt);
    pcol_kernel<<<dim3(32, 8), 192>>>(src, tgt);
    pband_kernel<<<32, 256>>>();
    mmd_gemm_kernel<<<dim3(36, 32), 256, SMEM_BYTES>>>();
    final_kernel<<<1, 32>>>(out);
}